// round 12
// baseline (speedup 1.0000x reference)
#include <cuda_runtime.h>
#include <cuda_bf16.h>

// Shapes (fixed): pos (256,100) f32, neg (256,4096,100) f32, lan (256,100) f32.
// out = mean((pos-lan)^2) + mean(relu(0.1 - mean_d((pos-neg)^2)))
//
// FINAL CONFIG (champion, measured 66.0 us): single fused kernel streaming
// feat_neg (419.4 MB, read-once) at ~6.4 TB/s — the B300 path-independent
// LTS/streaming ceiling. Bytes are algorithmically irreducible (nonlinear
// per-(b,c) hinge). Verified stable across 9 structural variants.

#define B_DIM   256
#define C_DIM   4096
#define D_DIM   100
#define MARGIN  0.1f
#define INV_D   (1.0f / 100.0f)
#define INV_BC  (1.0f / (256.0f * 4096.0f))
#define INV_BD  (1.0f / (256.0f * 100.0f))
#define GRID_X  (B_DIM * 16)   // 4096 blocks
#define NSLOT   32

// Device-global scratch (no allocations). Slots 128B apart (own L2 lines).
// Last block resets everything each call -> identical state every replay.
__device__ float    g_acc[NSLOT * 32];
__device__ unsigned g_count;

__device__ __forceinline__ float row_partial(float4 p, float4 n) {
    float dx = p.x - n.x, dy = p.y - n.y;
    float dz = p.z - n.z, dw = p.w - n.w;
    return dx * dx + dy * dy + dz * dz + dw * dw;
}

// ---------------------------------------------------------------------------
// grid = 4096 (16 chunks of 256 c-rows per b), block = 256 (8 warps).
// Warp-interleaved group order: at iteration t, warp w handles group t*8+w,
// so the block streams one contiguous sliding 12.8KB window (32 consecutive
// rows) -> max DRAM row locality. Rows reduced 4-at-a-time with a combined
// butterfly (9 shfls / 4 rows, 2.25 shfl/row), predicated hinge. 31 regs,
// ~92% occupancy.
// ---------------------------------------------------------------------------
__global__ void __launch_bounds__(256)
k_fused(const float* __restrict__ pos,
        const float* __restrict__ neg,
        const float* __restrict__ lan,
        float* __restrict__ out) {
    const int lane  = threadIdx.x & 31;
    const int warp  = threadIdx.x >> 5;
    const int b     = blockIdx.x >> 4;    // / 16
    const int chunk = blockIdx.x & 15;    // % 16
    const bool act  = (lane < 25);        // 25 float4 = 100 floats per row
    const bool hi16 = (lane & 16) != 0;
    const bool hi8  = (lane & 8) != 0;

    float4 p = make_float4(0.f, 0.f, 0.f, 0.f);
    if (act) p = *reinterpret_cast<const float4*>(pos + b * D_DIM + lane * 4);

    // Block-contiguous base; warp w starts at group w, strides by 8 groups.
    const float* base = neg + ((size_t)b * C_DIM + (size_t)chunk * 256) * D_DIM
                        + (size_t)warp * 4 * D_DIM + lane * 4;

    float acc2 = 0.f;
    #pragma unroll 2
    for (int it = 0; it < 8; ++it) {
        // iteration stride: 8 warps * 4 rows * D = 3200 floats
        const float* rb = base + (size_t)it * (8 * 4 * D_DIM);

        float4 n0, n1, n2, n3;
        if (act) {
            n0 = __ldcs(reinterpret_cast<const float4*>(rb + 0 * D_DIM));
            n1 = __ldcs(reinterpret_cast<const float4*>(rb + 1 * D_DIM));
            n2 = __ldcs(reinterpret_cast<const float4*>(rb + 2 * D_DIM));
            n3 = __ldcs(reinterpret_cast<const float4*>(rb + 3 * D_DIM));
        }

        float pa = 0.f, pb = 0.f, pc = 0.f, pd = 0.f;
        if (act) {
            pa = row_partial(p, n0);
            pb = row_partial(p, n1);
            pc = row_partial(p, n2);
            pd = row_partial(p, n3);
        }

        // Combined butterfly: 9 shfls reduce all 4 rows.
        float ua = __shfl_xor_sync(0xffffffffu, pa, 16);
        float ub = __shfl_xor_sync(0xffffffffu, pb, 16);
        float uc = __shfl_xor_sync(0xffffffffu, pc, 16);
        float ud = __shfl_xor_sync(0xffffffffu, pd, 16);
        float e = hi16 ? (pb + ub) : (pa + ua);   // 0-15: a, 16-31: b
        float f = hi16 ? (pd + ud) : (pc + uc);   // 0-15: c, 16-31: d

        float ue = __shfl_xor_sync(0xffffffffu, e, 8);
        float uf = __shfl_xor_sync(0xffffffffu, f, 8);
        float g = hi8 ? (f + uf) : (e + ue);      // 0-7:a, 8-15:c, 16-23:b, 24-31:d

        g += __shfl_xor_sync(0xffffffffu, g, 4);
        g += __shfl_xor_sync(0xffffffffu, g, 2);
        g += __shfl_xor_sync(0xffffffffu, g, 1);

        if ((lane & 7) == 0)                      // lanes 0,8,16,24 hold row sums
            acc2 += fmaxf(0.f, fmaf(g, -INV_D, MARGIN));
    }

    // ---- loss1: chunk-0 blocks handle their b's 100 elements ---------------
    float l1 = 0.f;
    if (chunk == 0 && threadIdx.x < D_DIM) {
        float d = pos[b * D_DIM + threadIdx.x] - lan[b * D_DIM + threadIdx.x];
        l1 = d * d;
    }

    // ---- warp reduce then block reduce --------------------------------------
    float v = acc2 * INV_BC + l1 * INV_BD;        // LAMDA = 1
    #pragma unroll
    for (int o = 16; o > 0; o >>= 1)
        v += __shfl_xor_sync(0xffffffffu, v, o);

    __shared__ float sred[8];
    if (lane == 0) sred[warp] = v;
    __syncthreads();

    if (threadIdx.x == 0) {
        float t = 0.f;
        #pragma unroll
        for (int w = 0; w < 8; ++w) t += sred[w];
        atomicAdd(&g_acc[(blockIdx.x & (NSLOT - 1)) * 32], t);
        __threadfence();
        unsigned done = atomicAdd(&g_count, 1u);
        if (done == GRID_X - 1) {
            float total = 0.f;
            #pragma unroll
            for (int s = 0; s < NSLOT; ++s) {
                total += atomicAdd(&g_acc[s * 32], 0.0f);  // atomic read
                g_acc[s * 32] = 0.f;                        // reset for replay
            }
            out[0] = total;
            g_count = 0u;
        }
    }
}

extern "C" void kernel_launch(void* const* d_in, const int* in_sizes, int n_in,
                              void* d_out, int out_size) {
    const float* feat_pos = (const float*)d_in[0];
    const float* feat_neg = (const float*)d_in[1];
    const float* feat_lan = (const float*)d_in[2];
    float* out = (float*)d_out;

    k_fused<<<GRID_X, 256>>>(feat_pos, feat_neg, feat_lan, out);
}

// round 13
// speedup vs baseline: 1.0495x; 1.0495x over previous
#include <cuda_runtime.h>
#include <cuda_bf16.h>

// Shapes (fixed): pos (256,100) f32, neg (256,4096,100) f32, lan (256,100) f32.
// out = mean((pos-lan)^2) + mean(relu(0.1 - mean_d((pos-neg)^2)))
//
// Champion family: single fused kernel streaming feat_neg (419.4 MB,
// read-once) at ~6.4 TB/s (B300 practical streaming ceiling). This round:
// finer CTA granularity (CHUNKS 16->32) to shrink end-of-kernel drain tail.

#define B_DIM   256
#define C_DIM   4096
#define D_DIM   100
#define MARGIN  0.1f
#define INV_D   (1.0f / 100.0f)
#define INV_BC  (1.0f / (256.0f * 4096.0f))
#define INV_BD  (1.0f / (256.0f * 100.0f))
#define CHUNKS  32
#define ROWS_PER_CHUNK (C_DIM / CHUNKS)          // 128
#define GRID_X  (B_DIM * CHUNKS)                 // 8192 blocks
#define NSLOT   32

// Device-global scratch (no allocations). Slots 128B apart (own L2 lines).
// Last block resets everything each call -> identical state every replay.
__device__ float    g_acc[NSLOT * 32];
__device__ unsigned g_count;

__device__ __forceinline__ float row_partial(float4 p, float4 n) {
    float dx = p.x - n.x, dy = p.y - n.y;
    float dz = p.z - n.z, dw = p.w - n.w;
    return dx * dx + dy * dy + dz * dz + dw * dw;
}

// ---------------------------------------------------------------------------
// grid = 8192 (32 chunks of 128 c-rows per b), block = 256 (8 warps).
// Warp-interleaved group order: at iteration t, warp w handles group t*8+w,
// so the block streams one contiguous sliding 12.8KB window (32 consecutive
// rows). Rows reduced 4-at-a-time with a combined butterfly (9 shfls /
// 4 rows), predicated hinge. 31 regs, ~92% occupancy.
// ---------------------------------------------------------------------------
__global__ void __launch_bounds__(256)
k_fused(const float* __restrict__ pos,
        const float* __restrict__ neg,
        const float* __restrict__ lan,
        float* __restrict__ out) {
    const int lane  = threadIdx.x & 31;
    const int warp  = threadIdx.x >> 5;
    const int b     = blockIdx.x >> 5;            // / CHUNKS
    const int chunk = blockIdx.x & (CHUNKS - 1);  // % CHUNKS
    const bool act  = (lane < 25);        // 25 float4 = 100 floats per row
    const bool hi16 = (lane & 16) != 0;
    const bool hi8  = (lane & 8) != 0;

    float4 p = make_float4(0.f, 0.f, 0.f, 0.f);
    if (act) p = *reinterpret_cast<const float4*>(pos + b * D_DIM + lane * 4);

    // Block-contiguous base; warp w starts at group w, strides by 8 groups.
    const float* base = neg
        + ((size_t)b * C_DIM + (size_t)chunk * ROWS_PER_CHUNK) * D_DIM
        + (size_t)warp * 4 * D_DIM + lane * 4;

    float acc2 = 0.f;
    #pragma unroll
    for (int it = 0; it < 4; ++it) {              // 4 iterations of 32 rows
        // iteration stride: 8 warps * 4 rows * D = 3200 floats
        const float* rb = base + (size_t)it * (8 * 4 * D_DIM);

        float4 n0, n1, n2, n3;
        if (act) {
            n0 = __ldcs(reinterpret_cast<const float4*>(rb + 0 * D_DIM));
            n1 = __ldcs(reinterpret_cast<const float4*>(rb + 1 * D_DIM));
            n2 = __ldcs(reinterpret_cast<const float4*>(rb + 2 * D_DIM));
            n3 = __ldcs(reinterpret_cast<const float4*>(rb + 3 * D_DIM));
        }

        float pa = 0.f, pb = 0.f, pc = 0.f, pd = 0.f;
        if (act) {
            pa = row_partial(p, n0);
            pb = row_partial(p, n1);
            pc = row_partial(p, n2);
            pd = row_partial(p, n3);
        }

        // Combined butterfly: 9 shfls reduce all 4 rows.
        float ua = __shfl_xor_sync(0xffffffffu, pa, 16);
        float ub = __shfl_xor_sync(0xffffffffu, pb, 16);
        float uc = __shfl_xor_sync(0xffffffffu, pc, 16);
        float ud = __shfl_xor_sync(0xffffffffu, pd, 16);
        float e = hi16 ? (pb + ub) : (pa + ua);   // 0-15: a, 16-31: b
        float f = hi16 ? (pd + ud) : (pc + uc);   // 0-15: c, 16-31: d

        float ue = __shfl_xor_sync(0xffffffffu, e, 8);
        float uf = __shfl_xor_sync(0xffffffffu, f, 8);
        float g = hi8 ? (f + uf) : (e + ue);      // 0-7:a, 8-15:c, 16-23:b, 24-31:d

        g += __shfl_xor_sync(0xffffffffu, g, 4);
        g += __shfl_xor_sync(0xffffffffu, g, 2);
        g += __shfl_xor_sync(0xffffffffu, g, 1);

        if ((lane & 7) == 0)                      // lanes 0,8,16,24 hold row sums
            acc2 += fmaxf(0.f, fmaf(g, -INV_D, MARGIN));
    }

    // ---- loss1: chunk-0 blocks handle their b's 100 elements ---------------
    float l1 = 0.f;
    if (chunk == 0 && threadIdx.x < D_DIM) {
        float d = pos[b * D_DIM + threadIdx.x] - lan[b * D_DIM + threadIdx.x];
        l1 = d * d;
    }

    // ---- warp reduce then block reduce --------------------------------------
    float v = acc2 * INV_BC + l1 * INV_BD;        // LAMDA = 1
    #pragma unroll
    for (int o = 16; o > 0; o >>= 1)
        v += __shfl_xor_sync(0xffffffffu, v, o);

    __shared__ float sred[8];
    if (lane == 0) sred[warp] = v;
    __syncthreads();

    if (threadIdx.x == 0) {
        float t = 0.f;
        #pragma unroll
        for (int w = 0; w < 8; ++w) t += sred[w];
        atomicAdd(&g_acc[(blockIdx.x & (NSLOT - 1)) * 32], t);
        __threadfence();
        unsigned done = atomicAdd(&g_count, 1u);
        if (done == GRID_X - 1) {
            float total = 0.f;
            #pragma unroll
            for (int s = 0; s < NSLOT; ++s) {
                total += atomicAdd(&g_acc[s * 32], 0.0f);  // atomic read
                g_acc[s * 32] = 0.f;                        // reset for replay
            }
            out[0] = total;
            g_count = 0u;
        }
    }
}

extern "C" void kernel_launch(void* const* d_in, const int* in_sizes, int n_in,
                              void* d_out, int out_size) {
    const float* feat_pos = (const float*)d_in[0];
    const float* feat_neg = (const float*)d_in[1];
    const float* feat_lan = (const float*)d_in[2];
    float* out = (float*)d_out;

    k_fused<<<GRID_X, 256>>>(feat_pos, feat_neg, feat_lan, out);
}